// round 6
// baseline (speedup 1.0000x reference)
#include <cuda_runtime.h>
#include <mma.h>
#include <math.h>

using namespace nvcuda;

#define S_LEN  128
#define NBATCH 2048
#define HID    128
#define G4     512
#define OUTDIM 128
#define NH     (NBATCH*HID)
#define M_ALL  (S_LEN*NBATCH)      // 262144 flattened rows

#define PITCH 132                  // 128 + 4 pad floats; 528B rows (16B aligned)
#define GEMM_SMEM ((128 + 64)*PITCH*4)   // 101376 B (all three GEMM kernels)

// ---------------- static device scratch (no cudaMalloc anywhere) ----------------
__device__ float g_xg  [(size_t)M_ALL*G4];       // 536 MB: x·W_ih^T for all steps (packed gate cols)
__device__ float g_hist[(size_t)M_ALL*HID];      // 134 MB: h_t history
__device__ float g_h[2*NH];                      // ping-pong hidden state
__device__ float g_c[NH];                        // cell state (disjoint per CTA)
__device__ float g_Wih_p[G4*HID];                // packed W_ih, tf32-rounded
__device__ float g_Whh_p[G4*HID];                // packed W_hh, tf32-rounded
__device__ float g_Wout_p[OUTDIM*HID];           // W_out, tf32-rounded
__device__ float g_bp[G4];                       // b_ih + b_hh, packed order

__device__ __forceinline__ float to_tf32(float x) {
    unsigned r;
    asm("cvt.rna.tf32.f32 %0, %1;" : "=r"(r) : "f"(x));
    return __uint_as_float(r);
}
__device__ __forceinline__ float sigm(float v) { return 1.0f/(1.0f + __expf(-v)); }

// Pack: packed row r = hb*128 + gate*32 + j  <->  orig row gate*128 + hb*32 + j.
// CTA hb then owns 128 contiguous rows covering all 4 gates for its 32 h-columns.
__global__ void pack_kernel(const float* __restrict__ W_ih, const float* __restrict__ W_hh,
                            const float* __restrict__ b_ih, const float* __restrict__ b_hh,
                            const float* __restrict__ W_out) {
    int idx = blockIdx.x*256 + threadIdx.x;      // 65536 = 512 rows * 128 k
    int row = idx >> 7;
    int k   = idx & 127;
    int hb = row >> 7, rem = row & 127, gate = rem >> 5, j = rem & 31;
    int orow = gate*128 + hb*32 + j;
    g_Wih_p[row*HID + k] = to_tf32(W_ih[orow*HID + k]);
    g_Whh_p[row*HID + k] = to_tf32(W_hh[orow*HID + k]);
    if (k == 0) g_bp[row] = b_ih[orow] + b_hh[orow];
    if (idx < OUTDIM*HID) g_Wout_p[idx] = to_tf32(W_out[idx]);
}

__global__ void zero_kernel() {
    int idx = blockIdx.x*256 + threadIdx.x;
    if (idx < NH) { g_h[idx] = 0.0f; g_c[idx] = 0.0f; }
}

// ------------- pre-GEMM: g_xg[m][g] = x[m][:] . Wih_p[g][:]  (m = s*N+n flat) -------------
// CTA tile 128(m) x 64(g); warps 4x2, each 32x32 via 2x2 m16n16k8 tf32 frags.
__global__ void __launch_bounds__(256) xg_gemm_kernel(const float* __restrict__ x) {
    extern __shared__ float sm[];
    float* sA = sm;                 // [128][PITCH]
    float* sB = sm + 128*PITCH;     // [64][PITCH]
    const int tid = threadIdx.x;
    const int m0 = blockIdx.x*128;
    const int n0 = blockIdx.y*64;

    const float* xr = x + (size_t)m0*HID;
    for (int e = tid; e < 128*32; e += 256) {
        int r = e >> 5, c4 = e & 31;
        float4 v = *(const float4*)(xr + r*HID + c4*4);
        float* d = &sA[r*PITCH + c4*4];
        d[0]=to_tf32(v.x); d[1]=to_tf32(v.y); d[2]=to_tf32(v.z); d[3]=to_tf32(v.w);
    }
    for (int e = tid; e < 64*32; e += 256) {
        int r = e >> 5, c4 = e & 31;
        *(float4*)&sB[r*PITCH + c4*4] = *(const float4*)(g_Wih_p + (size_t)(n0+r)*HID + c4*4);
    }
    __syncthreads();

    const int w = tid >> 5;
    const int wm = w & 3, wn = w >> 2;          // 4x2 warp grid
    wmma::fragment<wmma::accumulator,16,16,8,float> c[2][2];
    #pragma unroll
    for (int i=0;i<2;i++) { wmma::fill_fragment(c[i][0],0.f); wmma::fill_fragment(c[i][1],0.f); }

    #pragma unroll
    for (int k = 0; k < HID; k += 8) {
        wmma::fragment<wmma::matrix_a,16,16,8,wmma::precision::tf32,wmma::row_major> a0,a1;
        wmma::fragment<wmma::matrix_b,16,16,8,wmma::precision::tf32,wmma::col_major> b0,b1;
        wmma::load_matrix_sync(a0, &sA[(wm*32     )*PITCH + k], PITCH);
        wmma::load_matrix_sync(a1, &sA[(wm*32 + 16)*PITCH + k], PITCH);
        wmma::load_matrix_sync(b0, &sB[(wn*32     )*PITCH + k], PITCH);
        wmma::load_matrix_sync(b1, &sB[(wn*32 + 16)*PITCH + k], PITCH);
        wmma::mma_sync(c[0][0], a0, b0, c[0][0]);
        wmma::mma_sync(c[0][1], a0, b1, c[0][1]);
        wmma::mma_sync(c[1][0], a1, b0, c[1][0]);
        wmma::mma_sync(c[1][1], a1, b1, c[1][1]);
    }
    #pragma unroll
    for (int i=0;i<2;i++)
        #pragma unroll
        for (int j=0;j<2;j++)
            wmma::store_matrix_sync(&g_xg[(size_t)(m0 + wm*32 + i*16)*G4 + n0 + wn*32 + j*16],
                                    c[i][j], G4, wmma::mem_row_major);
}

// ------------- per-step: gates = xg[s] + h_{s-1}·Whh_p^T, then LSTM elementwise -------------
// Grid: 32 nb (64 samples) x 4 hb (128 packed gate rows). warps 2x4, warp tile 32x32.
__global__ void __launch_bounds__(256) lstm_step_kernel(int s) {
    extern __shared__ float sm[];
    float* sA = sm;                 // [64][PITCH]  h tile (tf32); reused as gate park
    float* sB = sm + 64*PITCH;      // [128][PITCH] Whh packed slice (tf32)
    const int tid = threadIdx.x;
    const int nb = blockIdx.x, hb = blockIdx.y;
    const int n0 = nb*64;

    const float* __restrict__ h_rd = g_h + (s & 1)*NH;
    float*       __restrict__ h_wr = g_h + ((s & 1) ^ 1)*NH;

    for (int e = tid; e < 64*32; e += 256) {
        int r = e >> 5, c4 = e & 31;
        float4 v = *(const float4*)(h_rd + (size_t)(n0+r)*HID + c4*4);
        float* d = &sA[r*PITCH + c4*4];
        d[0]=to_tf32(v.x); d[1]=to_tf32(v.y); d[2]=to_tf32(v.z); d[3]=to_tf32(v.w);
    }
    for (int e = tid; e < 128*32; e += 256) {
        int r = e >> 5, c4 = e & 31;
        *(float4*)&sB[r*PITCH + c4*4] = *(const float4*)(g_Whh_p + (size_t)(hb*128 + r)*HID + c4*4);
    }

    const int w = tid >> 5;
    const int wm = w & 1, wn = w >> 1;          // 2x4 warp grid
    wmma::fragment<wmma::accumulator,16,16,8,float> c[2][2];
    const float* xgp = g_xg + ((size_t)s*NBATCH + n0)*G4 + hb*128;
    #pragma unroll
    for (int i=0;i<2;i++)
        #pragma unroll
        for (int j=0;j<2;j++)
            wmma::load_matrix_sync(c[i][j], xgp + (size_t)(wm*32 + i*16)*G4 + wn*32 + j*16,
                                   G4, wmma::mem_row_major);
    __syncthreads();

    #pragma unroll
    for (int k = 0; k < HID; k += 8) {
        wmma::fragment<wmma::matrix_a,16,16,8,wmma::precision::tf32,wmma::row_major> a0,a1;
        wmma::fragment<wmma::matrix_b,16,16,8,wmma::precision::tf32,wmma::col_major> b0,b1;
        wmma::load_matrix_sync(a0, &sA[(wm*32     )*PITCH + k], PITCH);
        wmma::load_matrix_sync(a1, &sA[(wm*32 + 16)*PITCH + k], PITCH);
        wmma::load_matrix_sync(b0, &sB[(wn*32     )*PITCH + k], PITCH);
        wmma::load_matrix_sync(b1, &sB[(wn*32 + 16)*PITCH + k], PITCH);
        wmma::mma_sync(c[0][0], a0, b0, c[0][0]);
        wmma::mma_sync(c[0][1], a0, b1, c[0][1]);
        wmma::mma_sync(c[1][0], a1, b0, c[1][0]);
        wmma::mma_sync(c[1][1], a1, b1, c[1][1]);
    }
    __syncthreads();                             // done reading sA; repurpose as park
    #pragma unroll
    for (int i=0;i<2;i++)
        #pragma unroll
        for (int j=0;j<2;j++)
            wmma::store_matrix_sync(&sA[(wm*32 + i*16)*PITCH + wn*32 + j*16],
                                    c[i][j], PITCH, wmma::mem_row_major);
    __syncthreads();

    float* hist_s = g_hist + (size_t)s*NH;
    const float* bp = g_bp + hb*128;
    for (int e = tid; e < 2048; e += 256) {
        int n_l = e & 63;
        int j   = e >> 6;                        // 0..31 h within block
        const float* row = &sA[n_l*PITCH];
        float iv = sigm (row[     j] + bp[     j]);
        float fv = sigm (row[32 + j] + bp[32 + j]);
        float gv = tanhf(row[64 + j] + bp[64 + j]);
        float ov = sigm (row[96 + j] + bp[96 + j]);
        size_t addr = (size_t)(n0 + n_l)*HID + hb*32 + j;
        float cc = fv*g_c[addr] + iv*gv;
        float hh = ov*tanhf(cc);
        g_c[addr]    = cc;
        h_wr[addr]   = hh;
        hist_s[addr] = hh;
    }
}

// ------------- projection: out[m][o] = hist[m][:] . W_out[o][:] + b_out[o] -------------
// CTA tile 128(m) x 64(o); warps 4x2.
__global__ void __launch_bounds__(256) proj_kernel(const float* __restrict__ b_out,
                                                   float* __restrict__ out) {
    extern __shared__ float sm[];
    float* sA = sm;                 // [128][PITCH] hist tile (tf32); reused as park
    float* sB = sm + 128*PITCH;     // [64][PITCH]  W_out slice
    const int tid = threadIdx.x;
    const int m0 = blockIdx.x*128;
    const int n0 = blockIdx.y*64;

    for (int e = tid; e < 128*32; e += 256) {
        int r = e >> 5, c4 = e & 31;
        float4 v = *(const float4*)(g_hist + (size_t)(m0+r)*HID + c4*4);
        float* d = &sA[r*PITCH + c4*4];
        d[0]=to_tf32(v.x); d[1]=to_tf32(v.y); d[2]=to_tf32(v.z); d[3]=to_tf32(v.w);
    }
    for (int e = tid; e < 64*32; e += 256) {
        int r = e >> 5, c4 = e & 31;
        *(float4*)&sB[r*PITCH + c4*4] = *(const float4*)(g_Wout_p + (size_t)(n0+r)*HID + c4*4);
    }
    __syncthreads();

    const int w = tid >> 5;
    const int wm = w & 3, wn = w >> 2;
    wmma::fragment<wmma::accumulator,16,16,8,float> c[2][2];
    #pragma unroll
    for (int i=0;i<2;i++) { wmma::fill_fragment(c[i][0],0.f); wmma::fill_fragment(c[i][1],0.f); }

    #pragma unroll
    for (int k = 0; k < HID; k += 8) {
        wmma::fragment<wmma::matrix_a,16,16,8,wmma::precision::tf32,wmma::row_major> a0,a1;
        wmma::fragment<wmma::matrix_b,16,16,8,wmma::precision::tf32,wmma::col_major> b0,b1;
        wmma::load_matrix_sync(a0, &sA[(wm*32     )*PITCH + k], PITCH);
        wmma::load_matrix_sync(a1, &sA[(wm*32 + 16)*PITCH + k], PITCH);
        wmma::load_matrix_sync(b0, &sB[(wn*32     )*PITCH + k], PITCH);
        wmma::load_matrix_sync(b1, &sB[(wn*32 + 16)*PITCH + k], PITCH);
        wmma::mma_sync(c[0][0], a0, b0, c[0][0]);
        wmma::mma_sync(c[0][1], a0, b1, c[0][1]);
        wmma::mma_sync(c[1][0], a1, b0, c[1][0]);
        wmma::mma_sync(c[1][1], a1, b1, c[1][1]);
    }
    __syncthreads();                             // repurpose sA as park [128][<=128]
    #pragma unroll
    for (int i=0;i<2;i++)
        #pragma unroll
        for (int j=0;j<2;j++)
            wmma::store_matrix_sync(&sA[(wm*32 + i*16)*PITCH + wn*32 + j*16],
                                    c[i][j], PITCH, wmma::mem_row_major);
    __syncthreads();

    for (int e = tid; e < 128*64; e += 256) {
        int r = e >> 6, col = e & 63;
        out[(size_t)(m0 + r)*OUTDIM + n0 + col] = sA[r*PITCH + col] + b_out[n0 + col];
    }
}

extern "C" void kernel_launch(void* const* d_in, const int* in_sizes, int n_in,
                              void* d_out, int out_size) {
    const float* x     = (const float*)d_in[0];
    const float* W_ih  = (const float*)d_in[1];
    const float* W_hh  = (const float*)d_in[2];
    const float* b_ih  = (const float*)d_in[3];
    const float* b_hh  = (const float*)d_in[4];
    const float* W_out = (const float*)d_in[5];
    const float* b_out = (const float*)d_in[6];
    float* out = (float*)d_out;
    (void)in_sizes; (void)n_in; (void)out_size;

    cudaFuncSetAttribute(xg_gemm_kernel,   cudaFuncAttributeMaxDynamicSharedMemorySize, GEMM_SMEM);
    cudaFuncSetAttribute(lstm_step_kernel, cudaFuncAttributeMaxDynamicSharedMemorySize, GEMM_SMEM);
    cudaFuncSetAttribute(proj_kernel,      cudaFuncAttributeMaxDynamicSharedMemorySize, GEMM_SMEM);

    pack_kernel<<<256, 256>>>(W_ih, W_hh, b_ih, b_hh, W_out);
    zero_kernel<<<1024, 256>>>();
    xg_gemm_kernel<<<dim3(M_ALL/128, G4/64), 256, GEMM_SMEM>>>(x);

    for (int s = 0; s < S_LEN; s++)
        lstm_step_kernel<<<dim3(32, 4), 256, GEMM_SMEM>>>(s);

    proj_kernel<<<dim3(M_ALL/128, OUTDIM/64), 256, GEMM_SMEM>>>(b_out, out);
}

// round 7
// speedup vs baseline: 1.7478x; 1.7478x over previous
#include <cuda_runtime.h>
#include <mma.h>
#include <math.h>

using namespace nvcuda;

#define S_LEN  128
#define NBATCH 2048
#define HID    128
#define G4     512
#define KTOT   256
#define OUTDIM 128
#define NH     (NBATCH*HID)
#define M_ALL  (S_LEN*NBATCH)

#define NGRID  128                  // persistent grid: 32 nb x 4 hb (<=148 SMs -> co-resident)

#define APITCH 264                  // 256 + 8 pad floats (16B aligned rows)
#define WPITCH 264
#define PPITCH 132                  // proj pitch: 128 + 4

#define STEP_SMEM ((128*WPITCH + 64*APITCH)*4 + 512)      // W-resident + A tile + bias = 203264 B
#define PROJ_SMEM ((128 + 64)*PPITCH*4)                   // 101376 B

// ---------------- static device scratch (no cudaMalloc anywhere) ----------------
__device__ float g_hist[(size_t)M_ALL*HID];   // 134 MB: h_t history for projection
__device__ float g_h[2*NH];                   // ping-pong hidden state
__device__ float g_Wp[G4*KTOT];               // fused packed [W_ih | W_hh], tf32-rounded
__device__ float g_Wout_p[OUTDIM*HID];        // W_out, tf32-rounded
__device__ float g_bp[G4];                    // b_ih + b_hh, packed row order
__device__ unsigned g_bar_cnt;                // grid barrier arrival counter
__device__ unsigned g_bar_gen;                // grid barrier generation

__device__ __forceinline__ float to_tf32(float x) {
    unsigned r;
    asm("cvt.rna.tf32.f32 %0, %1;" : "=r"(r) : "f"(x));
    return __uint_as_float(r);
}
__device__ __forceinline__ float sigm(float v) { return 1.0f/(1.0f + __expf(-v)); }

// Pack: packed row r = hb*128 + gate*32 + j  <->  orig row gate*128 + hb*32 + j.
// Fused K: k<128 -> W_ih, k>=128 -> W_hh. CTA hb owns 128 contiguous packed rows.
__global__ void pack_kernel(const float* __restrict__ W_ih, const float* __restrict__ W_hh,
                            const float* __restrict__ b_ih, const float* __restrict__ b_hh,
                            const float* __restrict__ W_out) {
    int idx = blockIdx.x*256 + threadIdx.x;      // 512 rows * 256 k = 131072
    int row = idx >> 8;
    int k   = idx & 255;
    int hb = row >> 7, rem = row & 127, gate = rem >> 5, j = rem & 31;
    int orow = gate*128 + hb*32 + j;
    float v = (k < HID) ? W_ih[orow*HID + k] : W_hh[orow*HID + (k - HID)];
    g_Wp[row*KTOT + k] = to_tf32(v);
    if (k == 0) g_bp[row] = b_ih[orow] + b_hh[orow];
    if (idx < OUTDIM*HID) g_Wout_p[idx] = to_tf32(W_out[idx]);
}

__global__ void zero_kernel() {
    int idx = blockIdx.x*256 + threadIdx.x;
    if (idx < NH) g_h[idx] = 0.0f;               // h_0 = 0 (buffer 0)
    if (idx == 0) { g_bar_cnt = 0; g_bar_gen = 0; }
}

// ---------------- persistent recurrence kernel: all 128 steps in one launch ----------------
// Grid (32, 4): nb = 64-sample block, hb = 32 hidden cols (128 packed gate rows).
// W slice resident in smem for all steps; c state resident in registers.
__global__ void __launch_bounds__(256) lstm_persist_kernel(const float* __restrict__ x) {
    extern __shared__ float sm[];
    float* sW    = sm;                          // [128][WPITCH]  resident weight slice (tf32)
    float* sA    = sm + 128*WPITCH;             // [64][APITCH]   per-step A tile; reused as gate park
    float* sBias = sm + 128*WPITCH + 64*APITCH; // [128]

    const int tid = threadIdx.x;
    const int nb  = blockIdx.x;                 // 0..31
    const int hb  = blockIdx.y;                 // 0..3
    const int n0  = nb*64;

    // ---- one-time: stage weight slice + bias ----
    {
        const float* Wbase = g_Wp + (size_t)hb*128*KTOT;
        for (int e = tid; e < 128*64; e += 256) {           // 128 rows x 64 float4
            int r = e >> 6, c4 = e & 63;
            *(float4*)&sW[r*WPITCH + c4*4] = *(const float4*)(Wbase + (size_t)r*KTOT + c4*4);
        }
        if (tid < 128) sBias[tid] = g_bp[hb*128 + tid];
    }

    const int w  = tid >> 5;
    const int wm = w & 1;                       // 2 warp-rows  (samples)
    const int wn = w >> 1;                      // 4 warp-cols  (gate rows)
    const int n_l   = tid & 63;                 // epilogue: owned sample
    const int jbase = tid >> 6;                 // epilogue: j = jbase + 4*r

    float c_reg[8];
    #pragma unroll
    for (int r = 0; r < 8; r++) c_reg[r] = 0.0f;   // c_0 = 0

    for (int s = 0; s < S_LEN; s++) {
        // ---- stage A tile: sA[sample][k], k<128 = x_t, k>=128 = h_{s-1} ----
        const float* xs   = x   + ((size_t)s*NBATCH + n0)*HID;
        const float* h_rd = g_h + (size_t)(s & 1)*NH + (size_t)n0*HID;
        for (int e = tid; e < 64*32; e += 256) {            // 64 rows x 32 float4
            int r = e >> 5, c4 = e & 31;
            float4 vx = *(const float4*)(xs   + (size_t)r*HID + c4*4);
            float4 vh = *(const float4*)(h_rd + (size_t)r*HID + c4*4);
            float* dx = &sA[r*APITCH + c4*4];
            dx[0]=to_tf32(vx.x); dx[1]=to_tf32(vx.y); dx[2]=to_tf32(vx.z); dx[3]=to_tf32(vx.w);
            float* dh = dx + HID;
            dh[0]=to_tf32(vh.x); dh[1]=to_tf32(vh.y); dh[2]=to_tf32(vh.z); dh[3]=to_tf32(vh.w);
        }
        __syncthreads();

        // ---- GEMM: gates[64 x 128] = A[64 x 256] . W^T ----
        wmma::fragment<wmma::accumulator,16,16,8,float> c[2][2];
        #pragma unroll
        for (int i=0;i<2;i++) { wmma::fill_fragment(c[i][0],0.f); wmma::fill_fragment(c[i][1],0.f); }

        #pragma unroll
        for (int k = 0; k < KTOT; k += 8) {
            wmma::fragment<wmma::matrix_a,16,16,8,wmma::precision::tf32,wmma::row_major> a0,a1;
            wmma::fragment<wmma::matrix_b,16,16,8,wmma::precision::tf32,wmma::col_major> b0,b1;
            wmma::load_matrix_sync(a0, &sA[(wm*32     )*APITCH + k], APITCH);
            wmma::load_matrix_sync(a1, &sA[(wm*32 + 16)*APITCH + k], APITCH);
            wmma::load_matrix_sync(b0, &sW[(wn*32     )*WPITCH + k], WPITCH);
            wmma::load_matrix_sync(b1, &sW[(wn*32 + 16)*WPITCH + k], WPITCH);
            wmma::mma_sync(c[0][0], a0, b0, c[0][0]);
            wmma::mma_sync(c[0][1], a0, b1, c[0][1]);
            wmma::mma_sync(c[1][0], a1, b0, c[1][0]);
            wmma::mma_sync(c[1][1], a1, b1, c[1][1]);
        }
        __syncthreads();                         // all warps done reading sA -> park
        #pragma unroll
        for (int i=0;i<2;i++)
            #pragma unroll
            for (int j=0;j<2;j++)
                wmma::store_matrix_sync(&sA[(wm*32 + i*16)*APITCH + wn*32 + j*16],
                                        c[i][j], APITCH, wmma::mem_row_major);
        __syncthreads();

        // ---- elementwise LSTM update; c stays in registers ----
        float* h_wr   = g_h    + (size_t)((s & 1) ^ 1)*NH;
        float* hist_s = g_hist + (size_t)s*NH;
        const float* row = &sA[n_l*APITCH];
        #pragma unroll
        for (int r = 0; r < 8; r++) {
            int j = jbase + r*4;                 // 0..31
            float iv = sigm (row[     j] + sBias[     j]);
            float fv = sigm (row[32 + j] + sBias[32 + j]);
            float gv = tanhf(row[64 + j] + sBias[64 + j]);
            float ov = sigm (row[96 + j] + sBias[96 + j]);
            float cc = fv*c_reg[r] + iv*gv;
            float hh = ov*tanhf(cc);
            c_reg[r] = cc;
            size_t addr = (size_t)(n0 + n_l)*HID + hb*32 + j;
            h_wr[addr]   = hh;
            hist_s[addr] = hh;
        }

        // ---- grid barrier (CG-style) ----
        __syncthreads();
        if (tid == 0) {
            __threadfence();
            unsigned a = atomicAdd(&g_bar_cnt, 1);
            if (a == NGRID - 1) {
                g_bar_cnt = 0;
                __threadfence();
                atomicAdd(&g_bar_gen, 1);
            } else {
                unsigned target = (unsigned)(s + 1);
                while (*(volatile unsigned*)&g_bar_gen < target) { }
                __threadfence();
            }
        }
        __syncthreads();
    }
}

// ------------- projection: out[m][o] = hist[m][:] . W_out[o][:] + b_out[o] -------------
__global__ void __launch_bounds__(256) proj_kernel(const float* __restrict__ b_out,
                                                   float* __restrict__ out) {
    extern __shared__ float sm[];
    float* sA = sm;                 // [128][PPITCH] hist tile (tf32); reused as park
    float* sB = sm + 128*PPITCH;    // [64][PPITCH]  W_out slice
    const int tid = threadIdx.x;
    const int m0 = blockIdx.x*128;
    const int n0 = blockIdx.y*64;

    for (int e = tid; e < 128*32; e += 256) {
        int r = e >> 5, c4 = e & 31;
        float4 v = *(const float4*)(g_hist + (size_t)(m0+r)*HID + c4*4);
        float* d = &sA[r*PPITCH + c4*4];
        d[0]=to_tf32(v.x); d[1]=to_tf32(v.y); d[2]=to_tf32(v.z); d[3]=to_tf32(v.w);
    }
    for (int e = tid; e < 64*32; e += 256) {
        int r = e >> 5, c4 = e & 31;
        *(float4*)&sB[r*PPITCH + c4*4] = *(const float4*)(g_Wout_p + (size_t)(n0+r)*HID + c4*4);
    }
    __syncthreads();

    const int w = tid >> 5;
    const int wm = w & 3, wn = w >> 2;
    wmma::fragment<wmma::accumulator,16,16,8,float> c[2][2];
    #pragma unroll
    for (int i=0;i<2;i++) { wmma::fill_fragment(c[i][0],0.f); wmma::fill_fragment(c[i][1],0.f); }

    #pragma unroll
    for (int k = 0; k < HID; k += 8) {
        wmma::fragment<wmma::matrix_a,16,16,8,wmma::precision::tf32,wmma::row_major> a0,a1;
        wmma::fragment<wmma::matrix_b,16,16,8,wmma::precision::tf32,wmma::col_major> b0,b1;
        wmma::load_matrix_sync(a0, &sA[(wm*32     )*PPITCH + k], PPITCH);
        wmma::load_matrix_sync(a1, &sA[(wm*32 + 16)*PPITCH + k], PPITCH);
        wmma::load_matrix_sync(b0, &sB[(wn*32     )*PPITCH + k], PPITCH);
        wmma::load_matrix_sync(b1, &sB[(wn*32 + 16)*PPITCH + k], PPITCH);
        wmma::mma_sync(c[0][0], a0, b0, c[0][0]);
        wmma::mma_sync(c[0][1], a0, b1, c[0][1]);
        wmma::mma_sync(c[1][0], a1, b0, c[1][0]);
        wmma::mma_sync(c[1][1], a1, b1, c[1][1]);
    }
    __syncthreads();
    #pragma unroll
    for (int i=0;i<2;i++)
        #pragma unroll
        for (int j=0;j<2;j++)
            wmma::store_matrix_sync(&sA[(wm*32 + i*16)*PPITCH + wn*32 + j*16],
                                    c[i][j], PPITCH, wmma::mem_row_major);
    __syncthreads();

    for (int e = tid; e < 128*64; e += 256) {
        int r = e >> 6, col = e & 63;
        out[(size_t)(m0 + r)*OUTDIM + n0 + col] = sA[r*PPITCH + col] + b_out[n0 + col];
    }
}

extern "C" void kernel_launch(void* const* d_in, const int* in_sizes, int n_in,
                              void* d_out, int out_size) {
    const float* x     = (const float*)d_in[0];
    const float* W_ih  = (const float*)d_in[1];
    const float* W_hh  = (const float*)d_in[2];
    const float* b_ih  = (const float*)d_in[3];
    const float* b_hh  = (const float*)d_in[4];
    const float* W_out = (const float*)d_in[5];
    const float* b_out = (const float*)d_in[6];
    float* out = (float*)d_out;
    (void)in_sizes; (void)n_in; (void)out_size;

    cudaFuncSetAttribute(lstm_persist_kernel, cudaFuncAttributeMaxDynamicSharedMemorySize, STEP_SMEM);
    cudaFuncSetAttribute(proj_kernel,         cudaFuncAttributeMaxDynamicSharedMemorySize, PROJ_SMEM);

    pack_kernel<<<512, 256>>>(W_ih, W_hh, b_ih, b_hh, W_out);
    zero_kernel<<<1024, 256>>>();

    lstm_persist_kernel<<<dim3(32, 4), 256, STEP_SMEM>>>(x);

    proj_kernel<<<dim3(M_ALL/128, OUTDIM/64), 256, PROJ_SMEM>>>(b_out, out);
}

// round 8
// speedup vs baseline: 2.3628x; 1.3518x over previous
#include <cuda_runtime.h>
#include <mma.h>
#include <math.h>

using namespace nvcuda;

#define S_LEN  128
#define NBATCH 2048
#define HID    128
#define G4     512
#define KTOT   256
#define OUTDIM 128
#define NH     (NBATCH*HID)
#define M_ALL  (S_LEN*NBATCH)

#define APITCH 264                  // 256 + 8 pad floats
#define WPITCH 264
#define PPITCH 132                  // proj pitch: 128 + 4

#define STEP_SMEM ((128*WPITCH + 64*APITCH)*4 + 512)      // 203264 B
#define PROJ_SMEM ((128 + 64)*PPITCH*4)                   // 101376 B

#define CLUSTER_SYNC() do { \
    asm volatile("barrier.cluster.arrive.aligned;" ::: "memory"); \
    asm volatile("barrier.cluster.wait.aligned;"   ::: "memory"); \
} while (0)

// ---------------- static device scratch (no cudaMalloc anywhere) ----------------
__device__ float g_hist[(size_t)M_ALL*HID];   // h_t history (tf32-rounded) — also the h exchange medium
__device__ float g_Wp[G4*KTOT];               // fused packed [W_ih | W_hh], tf32-rounded
__device__ float g_Wout_p[OUTDIM*HID];        // W_out, tf32-rounded
__device__ float g_bp[G4];                    // b_ih + b_hh, packed row order

__device__ __forceinline__ float to_tf32(float x) {
    unsigned r;
    asm("cvt.rna.tf32.f32 %0, %1;" : "=r"(r) : "f"(x));
    return __uint_as_float(r);
}
__device__ __forceinline__ float sigm(float v) { return 1.0f/(1.0f + __expf(-v)); }

// Pack: packed row r = hb*128 + gate*32 + j  <->  orig row gate*128 + hb*32 + j.
__global__ void pack_kernel(const float* __restrict__ W_ih, const float* __restrict__ W_hh,
                            const float* __restrict__ b_ih, const float* __restrict__ b_hh,
                            const float* __restrict__ W_out) {
    int idx = blockIdx.x*256 + threadIdx.x;      // 512 rows * 256 k
    int row = idx >> 8;
    int k   = idx & 255;
    int hb = row >> 7, rem = row & 127, gate = rem >> 5, j = rem & 31;
    int orow = gate*128 + hb*32 + j;
    float v = (k < HID) ? W_ih[orow*HID + k] : W_hh[orow*HID + (k - HID)];
    g_Wp[row*KTOT + k] = to_tf32(v);
    if (k == 0) g_bp[row] = b_ih[orow] + b_hh[orow];
    if (idx < OUTDIM*HID) g_Wout_p[idx] = to_tf32(W_out[idx]);
}

// ---------------- persistent recurrence: all 128 steps, clusters of 4 hb-CTAs ----------------
// Grid (32, 4), cluster (1,4,1): cluster = the 4 hb CTAs sharing one nb (64 samples).
// h exchange goes through g_hist (slot per step -> no WAR); only a cluster barrier per step.
__global__ void __launch_bounds__(256) __cluster_dims__(1, 4, 1)
lstm_persist_kernel(const float* __restrict__ x) {
    extern __shared__ float sm[];
    float* sW    = sm;                          // [128][WPITCH]  resident weight slice (tf32)
    float* sA    = sm + 128*WPITCH;             // [64][APITCH]   A tile: cols 0..127 x_t (later gate park), 128..255 h
    float* sBias = sm + 128*WPITCH + 64*APITCH; // [128]

    const int tid = threadIdx.x;
    const int nb  = blockIdx.x;
    const int hb  = blockIdx.y;
    const int n0  = nb*64;

    {   // one-time: weight slice + bias
        const float* Wbase = g_Wp + (size_t)hb*128*KTOT;
        for (int e = tid; e < 128*64; e += 256) {
            int r = e >> 6, c4 = e & 63;
            *(float4*)&sW[r*WPITCH + c4*4] = *(const float4*)(Wbase + (size_t)r*KTOT + c4*4);
        }
        if (tid < 128) sBias[tid] = g_bp[hb*128 + tid];
    }

    const int w  = tid >> 5;
    const int wm = w & 1;                       // 2 warp-rows (samples)
    const int wn = w >> 1;                      // 4 warp-cols (gate rows)
    const int n_l = tid & 63;                   // epilogue: owned sample
    const int jg  = tid >> 6;                   // epilogue: j = jg*8 + q (contiguous octet)

    float c_reg[8];
    #pragma unroll
    for (int q = 0; q < 8; q++) c_reg[q] = 0.0f;

    // prefetch x(0) into registers: 8 float4/thread covering 64x128 floats
    float4 xreg[8];
    {
        const float* xs = x + (size_t)n0*HID;
        #pragma unroll
        for (int i = 0; i < 8; i++) {
            int e = tid + i*256, r = e >> 5, c4 = e & 31;
            xreg[i] = *(const float4*)(xs + (size_t)r*HID + c4*4);
        }
    }

    for (int s = 0; s < S_LEN; s++) {
        // ---- issue h_{s-1} loads to registers (hist is pre-tf32-rounded) ----
        float4 hreg[8];
        if (s > 0) {
            const float* hp = g_hist + (size_t)(s-1)*NH + (size_t)n0*HID;
            #pragma unroll
            for (int i = 0; i < 8; i++) {
                int e = tid + i*256, r = e >> 5, c4 = e & 31;
                hreg[i] = *(const float4*)(hp + (size_t)r*HID + c4*4);
            }
        } else {
            #pragma unroll
            for (int i = 0; i < 8; i++) hreg[i] = make_float4(0.f,0.f,0.f,0.f);
        }

        // ---- stage x half (consume prefetch, cvt to tf32) ----
        #pragma unroll
        for (int i = 0; i < 8; i++) {
            int e = tid + i*256, r = e >> 5, c4 = e & 31;
            float* d = &sA[r*APITCH + c4*4];
            d[0]=to_tf32(xreg[i].x); d[1]=to_tf32(xreg[i].y);
            d[2]=to_tf32(xreg[i].z); d[3]=to_tf32(xreg[i].w);
        }
        // ---- prefetch x(s+1) (flies during GEMM) ----
        {
            int sn = (s + 1 < S_LEN) ? s + 1 : s;
            const float* xs = x + ((size_t)sn*NBATCH + n0)*HID;
            #pragma unroll
            for (int i = 0; i < 8; i++) {
                int e = tid + i*256, r = e >> 5, c4 = e & 31;
                xreg[i] = *(const float4*)(xs + (size_t)r*HID + c4*4);
            }
        }
        __syncthreads();

        // ---- GEMM half 1: k = 0..127 (x part) while h loads complete ----
        wmma::fragment<wmma::accumulator,16,16,8,float> c[2][2];
        #pragma unroll
        for (int i=0;i<2;i++) { wmma::fill_fragment(c[i][0],0.f); wmma::fill_fragment(c[i][1],0.f); }

        #pragma unroll
        for (int k = 0; k < 128; k += 8) {
            wmma::fragment<wmma::matrix_a,16,16,8,wmma::precision::tf32,wmma::row_major> a0,a1;
            wmma::fragment<wmma::matrix_b,16,16,8,wmma::precision::tf32,wmma::col_major> b0,b1;
            wmma::load_matrix_sync(a0, &sA[(wm*32     )*APITCH + k], APITCH);
            wmma::load_matrix_sync(a1, &sA[(wm*32 + 16)*APITCH + k], APITCH);
            wmma::load_matrix_sync(b0, &sW[(wn*32     )*WPITCH + k], WPITCH);
            wmma::load_matrix_sync(b1, &sW[(wn*32 + 16)*WPITCH + k], WPITCH);
            wmma::mma_sync(c[0][0], a0, b0, c[0][0]);
            wmma::mma_sync(c[0][1], a0, b1, c[0][1]);
            wmma::mma_sync(c[1][0], a1, b0, c[1][0]);
            wmma::mma_sync(c[1][1], a1, b1, c[1][1]);
        }

        // ---- stage h half (no cvt needed) ----
        #pragma unroll
        for (int i = 0; i < 8; i++) {
            int e = tid + i*256, r = e >> 5, c4 = e & 31;
            *(float4*)&sA[r*APITCH + 128 + c4*4] = hreg[i];
        }
        __syncthreads();

        // ---- GEMM half 2: k = 128..255 (h part) ----
        #pragma unroll
        for (int k = 128; k < 256; k += 8) {
            wmma::fragment<wmma::matrix_a,16,16,8,wmma::precision::tf32,wmma::row_major> a0,a1;
            wmma::fragment<wmma::matrix_b,16,16,8,wmma::precision::tf32,wmma::col_major> b0,b1;
            wmma::load_matrix_sync(a0, &sA[(wm*32     )*APITCH + k], APITCH);
            wmma::load_matrix_sync(a1, &sA[(wm*32 + 16)*APITCH + k], APITCH);
            wmma::load_matrix_sync(b0, &sW[(wn*32     )*WPITCH + k], WPITCH);
            wmma::load_matrix_sync(b1, &sW[(wn*32 + 16)*WPITCH + k], WPITCH);
            wmma::mma_sync(c[0][0], a0, b0, c[0][0]);
            wmma::mma_sync(c[0][1], a0, b1, c[0][1]);
            wmma::mma_sync(c[1][0], a1, b0, c[1][0]);
            wmma::mma_sync(c[1][1], a1, b1, c[1][1]);
        }
        __syncthreads();

        // ---- park gates into X region (cols 0..127); x_s dead, x_{s+1} in regs ----
        #pragma unroll
        for (int i=0;i<2;i++)
            #pragma unroll
            for (int j=0;j<2;j++)
                wmma::store_matrix_sync(&sA[(wm*32 + i*16)*APITCH + wn*32 + j*16],
                                        c[i][j], APITCH, wmma::mem_row_major);
        __syncthreads();

        // ---- elementwise LSTM; c in registers; h (tf32-rounded) -> hist[s] ----
        {
            const float* row = &sA[n_l*APITCH];
            float hq[8];
            #pragma unroll
            for (int q = 0; q < 8; q++) {
                int j = jg*8 + q;
                float iv = sigm (row[     j] + sBias[     j]);
                float fv = sigm (row[32 + j] + sBias[32 + j]);
                float gv = tanhf(row[64 + j] + sBias[64 + j]);
                float ov = sigm (row[96 + j] + sBias[96 + j]);
                float cc = fv*c_reg[q] + iv*gv;
                c_reg[q] = cc;
                hq[q] = to_tf32(ov*tanhf(cc));
            }
            float* hp = g_hist + (size_t)s*NH + (size_t)(n0 + n_l)*HID + hb*32 + jg*8;
            *(float4*)(hp)     = make_float4(hq[0], hq[1], hq[2], hq[3]);
            *(float4*)(hp + 4) = make_float4(hq[4], hq[5], hq[6], hq[7]);
        }

        // ---- cluster barrier: release my hist[s] writes to hb-peers ----
        __syncthreads();
        CLUSTER_SYNC();
    }
}

// ------------- projection: out[m][o] = hist[m][:] . W_out[o][:] + b_out[o] -------------
// hist already tf32-rounded -> straight copies. launch_bounds(256,2): 2 CTAs/SM.
__global__ void __launch_bounds__(256, 2) proj_kernel(const float* __restrict__ b_out,
                                                      float* __restrict__ out) {
    extern __shared__ float sm[];
    float* sA = sm;                 // [128][PPITCH] hist tile; reused as park
    float* sB = sm + 128*PPITCH;    // [64][PPITCH]  W_out slice
    const int tid = threadIdx.x;
    const int m0 = blockIdx.x*128;
    const int n0 = blockIdx.y*64;

    for (int e = tid; e < 128*32; e += 256) {
        int r = e >> 5, c4 = e & 31;
        *(float4*)&sA[r*PPITCH + c4*4] = *(const float4*)(g_hist + (size_t)(m0+r)*HID + c4*4);
    }
    for (int e = tid; e < 64*32; e += 256) {
        int r = e >> 5, c4 = e & 31;
        *(float4*)&sB[r*PPITCH + c4*4] = *(const float4*)(g_Wout_p + (size_t)(n0+r)*HID + c4*4);
    }
    __syncthreads();

    const int w = tid >> 5;
    const int wm = w & 3, wn = w >> 2;
    wmma::fragment<wmma::accumulator,16,16,8,float> c[2][2];
    #pragma unroll
    for (int i=0;i<2;i++) { wmma::fill_fragment(c[i][0],0.f); wmma::fill_fragment(c[i][1],0.f); }

    #pragma unroll
    for (int k = 0; k < HID; k += 8) {
        wmma::fragment<wmma::matrix_a,16,16,8,wmma::precision::tf32,wmma::row_major> a0,a1;
        wmma::fragment<wmma::matrix_b,16,16,8,wmma::precision::tf32,wmma::col_major> b0,b1;
        wmma::load_matrix_sync(a0, &sA[(wm*32     )*PPITCH + k], PPITCH);
        wmma::load_matrix_sync(a1, &sA[(wm*32 + 16)*PPITCH + k], PPITCH);
        wmma::load_matrix_sync(b0, &sB[(wn*32     )*PPITCH + k], PPITCH);
        wmma::load_matrix_sync(b1, &sB[(wn*32 + 16)*PPITCH + k], PPITCH);
        wmma::mma_sync(c[0][0], a0, b0, c[0][0]);
        wmma::mma_sync(c[0][1], a0, b1, c[0][1]);
        wmma::mma_sync(c[1][0], a1, b0, c[1][0]);
        wmma::mma_sync(c[1][1], a1, b1, c[1][1]);
    }
    __syncthreads();
    #pragma unroll
    for (int i=0;i<2;i++)
        #pragma unroll
        for (int j=0;j<2;j++)
            wmma::store_matrix_sync(&sA[(wm*32 + i*16)*PPITCH + wn*32 + j*16],
                                    c[i][j], PPITCH, wmma::mem_row_major);
    __syncthreads();

    for (int e = tid; e < 128*16; e += 256) {   // float4 epilogue
        int r = e >> 4, c4 = e & 15;
        const float* p = &sA[r*PPITCH + c4*4];
        const float* b = &b_out[n0 + c4*4];
        float4 v = make_float4(p[0]+b[0], p[1]+b[1], p[2]+b[2], p[3]+b[3]);
        *(float4*)&out[(size_t)(m0 + r)*OUTDIM + n0 + c4*4] = v;
    }
}

extern "C" void kernel_launch(void* const* d_in, const int* in_sizes, int n_in,
                              void* d_out, int out_size) {
    const float* x     = (const float*)d_in[0];
    const float* W_ih  = (const float*)d_in[1];
    const float* W_hh  = (const float*)d_in[2];
    const float* b_ih  = (const float*)d_in[3];
    const float* b_hh  = (const float*)d_in[4];
    const float* W_out = (const float*)d_in[5];
    const float* b_out = (const float*)d_in[6];
    float* out = (float*)d_out;
    (void)in_sizes; (void)n_in; (void)out_size;

    cudaFuncSetAttribute(lstm_persist_kernel, cudaFuncAttributeMaxDynamicSharedMemorySize, STEP_SMEM);
    cudaFuncSetAttribute(proj_kernel,         cudaFuncAttributeMaxDynamicSharedMemorySize, PROJ_SMEM);

    pack_kernel<<<512, 256>>>(W_ih, W_hh, b_ih, b_hh, W_out);

    lstm_persist_kernel<<<dim3(32, 4), 256, STEP_SMEM>>>(x);

    proj_kernel<<<dim3(M_ALL/128, OUTDIM/64), 256, PROJ_SMEM>>>(b_out, out);
}

// round 9
// speedup vs baseline: 2.5532x; 1.0806x over previous
#include <cuda_runtime.h>
#include <mma.h>
#include <math.h>

using namespace nvcuda;

#define S_LEN  128
#define NBATCH 2048
#define HID    128
#define G4     512
#define KTOT   256
#define OUTDIM 128
#define NH     (NBATCH*HID)
#define M_ALL  (S_LEN*NBATCH)

#define APITCH 264                  // 256 + 8 pad floats (rows 16B aligned)
#define WPITCH 264
#define PPITCH 132

#define STEP_SMEM ((128*WPITCH + 64*APITCH)*4 + 512)      // 203264 B
#define PROJ_SMEM ((128 + 64)*PPITCH*4)                   // 101376 B

#define CLUSTER_SYNC() do { \
    asm volatile("barrier.cluster.arrive.aligned;" ::: "memory"); \
    asm volatile("barrier.cluster.wait.aligned;"   ::: "memory"); \
} while (0)

#define BARH(id) asm volatile("bar.sync %0, 256;" :: "r"(id) : "memory")

// ---------------- static device scratch (no cudaMalloc anywhere) ----------------
__device__ float g_hist[(size_t)M_ALL*HID];   // h_t history (tf32-rounded) — also the h exchange medium
__device__ float g_Wp[G4*KTOT];               // fused packed [W_ih | W_hh], tf32-rounded
__device__ float g_Wout_p[OUTDIM*HID];        // W_out, tf32-rounded
__device__ float g_bp[G4];                    // b_ih + b_hh, packed row order

__device__ __forceinline__ float to_tf32(float x) {
    unsigned r;
    asm("cvt.rna.tf32.f32 %0, %1;" : "=r"(r) : "f"(x));
    return __uint_as_float(r);
}
__device__ __forceinline__ float sigm(float v) { return 1.0f/(1.0f + __expf(-v)); }

// Pack: packed row r = hb*128 + gate*32 + j  <->  orig row gate*128 + hb*32 + j.
__global__ void pack_kernel(const float* __restrict__ W_ih, const float* __restrict__ W_hh,
                            const float* __restrict__ b_ih, const float* __restrict__ b_hh,
                            const float* __restrict__ W_out) {
    int idx = blockIdx.x*256 + threadIdx.x;      // 512 rows * 256 k
    int row = idx >> 8;
    int k   = idx & 255;
    int hb = row >> 7, rem = row & 127, gate = rem >> 5, j = rem & 31;
    int orow = gate*128 + hb*32 + j;
    float v = (k < HID) ? W_ih[orow*HID + k] : W_hh[orow*HID + (k - HID)];
    g_Wp[row*KTOT + k] = to_tf32(v);
    if (k == 0) g_bp[row] = b_ih[orow] + b_hh[orow];
    if (idx < OUTDIM*HID) g_Wout_p[idx] = to_tf32(W_out[idx]);
}

// One K-half of the gate GEMM + park. Warps of one 256-thread group: 2 (m) x 4 (n).
__device__ __forceinline__ void gemm_half(float* sA, const float* sW,
                                          int k0, int wm, int wn, int bar_id) {
    wmma::fragment<wmma::accumulator,16,16,8,float> c[2][2];
    #pragma unroll
    for (int i=0;i<2;i++) { wmma::fill_fragment(c[i][0],0.f); wmma::fill_fragment(c[i][1],0.f); }

    #pragma unroll
    for (int kk = 0; kk < 128; kk += 8) {
        const int k = k0 + kk;
        wmma::fragment<wmma::matrix_a,16,16,8,wmma::precision::tf32,wmma::row_major> a0,a1;
        wmma::fragment<wmma::matrix_b,16,16,8,wmma::precision::tf32,wmma::col_major> b0,b1;
        wmma::load_matrix_sync(a0, &sA[(wm*32     )*APITCH + k], APITCH);
        wmma::load_matrix_sync(a1, &sA[(wm*32 + 16)*APITCH + k], APITCH);
        wmma::load_matrix_sync(b0, &sW[(wn*32     )*WPITCH + k], WPITCH);
        wmma::load_matrix_sync(b1, &sW[(wn*32 + 16)*WPITCH + k], WPITCH);
        wmma::mma_sync(c[0][0], a0, b0, c[0][0]);
        wmma::mma_sync(c[0][1], a0, b1, c[0][1]);
        wmma::mma_sync(c[1][0], a1, b0, c[1][0]);
        wmma::mma_sync(c[1][1], a1, b1, c[1][1]);
    }
    BARH(bar_id);                                // whole group done reading its A region
    #pragma unroll
    for (int i=0;i<2;i++)
        #pragma unroll
        for (int j=0;j<2;j++)
            wmma::store_matrix_sync(&sA[(wm*32 + i*16)*APITCH + k0 + wn*32 + j*16],
                                    c[i][j], APITCH, wmma::mem_row_major);
}

// ---------------- persistent recurrence: 512 threads, split-K warp groups ----------------
// Grid (32, 4), cluster (1,4,1). Warps 0-7: x half (k<128); warps 8-15: h half (k>=128).
__global__ void __launch_bounds__(512) __cluster_dims__(1, 4, 1)
lstm_persist_kernel(const float* __restrict__ x) {
    extern __shared__ float sm[];
    float* sW    = sm;                          // [128][WPITCH]  resident weight slice (tf32)
    float* sA    = sm + 128*WPITCH;             // [64][APITCH]   A tile; later dual gate park
    float* sBias = sm + 128*WPITCH + 64*APITCH; // [128]

    const int tid = threadIdx.x;
    const int nb  = blockIdx.x;
    const int hb  = blockIdx.y;
    const int n0  = nb*64;

    {   // one-time: weight slice + bias
        const float* Wbase = g_Wp + (size_t)hb*128*KTOT;
        for (int e = tid; e < 128*64; e += 512) {
            int r = e >> 6, c4 = e & 63;
            *(float4*)&sW[r*WPITCH + c4*4] = *(const float4*)(Wbase + (size_t)r*KTOT + c4*4);
        }
        if (tid < 128) sBias[tid] = g_bp[hb*128 + tid];
    }

    const int w2 = (tid >> 5) & 7;
    const int wm = w2 & 1;                      // 2 warp-rows (samples)
    const int wn = w2 >> 1;                     // 4 warp-cols (gate rows)
    const bool grp_x = (tid < 256);
    const int  t2    = tid & 255;

    // epilogue mapping: conflict-free float4 reads
    const int n_l = tid >> 3;                   // 0..63
    const int jg  = tid & 7;                    // j = jg*4 + q

    float c_reg[4];
    #pragma unroll
    for (int q = 0; q < 4; q++) c_reg[q] = 0.0f;

    float4 xreg[8];
    if (grp_x) {                                // prefetch x(0)
        const float* xs = x + (size_t)n0*HID;
        #pragma unroll
        for (int i = 0; i < 8; i++) {
            int e = t2 + i*256, r = e >> 5, c4 = e & 31;
            xreg[i] = *(const float4*)(xs + (size_t)r*HID + c4*4);
        }
    }
    __syncthreads();                            // sW/sBias ready

    for (int s = 0; s < S_LEN; s++) {
        if (grp_x) {
            // stage x(s) (cvt to tf32), prefetch x(s+1), then x-half GEMM
            #pragma unroll
            for (int i = 0; i < 8; i++) {
                int e = t2 + i*256, r = e >> 5, c4 = e & 31;
                float* d = &sA[r*APITCH + c4*4];
                d[0]=to_tf32(xreg[i].x); d[1]=to_tf32(xreg[i].y);
                d[2]=to_tf32(xreg[i].z); d[3]=to_tf32(xreg[i].w);
            }
            {
                int sn = (s + 1 < S_LEN) ? s + 1 : s;
                const float* xs = x + ((size_t)sn*NBATCH + n0)*HID;
                #pragma unroll
                for (int i = 0; i < 8; i++) {
                    int e = t2 + i*256, r = e >> 5, c4 = e & 31;
                    xreg[i] = *(const float4*)(xs + (size_t)r*HID + c4*4);
                }
            }
            BARH(1);
            gemm_half(sA, sW, 0, wm, wn, 1);
        } else {
            // stage h(s-1) (hist is pre-tf32-rounded), then h-half GEMM
            if (s > 0) {
                const float* hp = g_hist + (size_t)(s-1)*NH + (size_t)n0*HID;
                #pragma unroll
                for (int i = 0; i < 8; i++) {
                    int e = t2 + i*256, r = e >> 5, c4 = e & 31;
                    *(float4*)&sA[r*APITCH + 128 + c4*4] = *(const float4*)(hp + (size_t)r*HID + c4*4);
                }
            } else {
                float4 z = make_float4(0.f,0.f,0.f,0.f);
                #pragma unroll
                for (int i = 0; i < 8; i++) {
                    int e = t2 + i*256, r = e >> 5, c4 = e & 31;
                    *(float4*)&sA[r*APITCH + 128 + c4*4] = z;
                }
            }
            BARH(2);
            gemm_half(sA, sW, 128, wm, wn, 2);
        }
        __syncthreads();                        // both parks complete

        // ---- elementwise LSTM: sum the two K-half parks + bias; c in regs ----
        {
            const float* row = &sA[n_l*APITCH];
            const int j0 = jg*4;
            float4 iA = *(const float4*)&row[          j0];
            float4 iB = *(const float4*)&row[128 +     j0];
            float4 fA = *(const float4*)&row[ 32 +     j0];
            float4 fB = *(const float4*)&row[128 + 32 + j0];
            float4 gA = *(const float4*)&row[ 64 +     j0];
            float4 gB = *(const float4*)&row[128 + 64 + j0];
            float4 oA = *(const float4*)&row[ 96 +     j0];
            float4 oB = *(const float4*)&row[128 + 96 + j0];
            float4 bi = *(const float4*)&sBias[      j0];
            float4 bf = *(const float4*)&sBias[ 32 + j0];
            float4 bg = *(const float4*)&sBias[ 64 + j0];
            float4 bo = *(const float4*)&sBias[ 96 + j0];

            float iv[4] = {iA.x+iB.x+bi.x, iA.y+iB.y+bi.y, iA.z+iB.z+bi.z, iA.w+iB.w+bi.w};
            float fv[4] = {fA.x+fB.x+bf.x, fA.y+fB.y+bf.y, fA.z+fB.z+bf.z, fA.w+fB.w+bf.w};
            float gv[4] = {gA.x+gB.x+bg.x, gA.y+gB.y+bg.y, gA.z+gB.z+bg.z, gA.w+gB.w+bg.w};
            float ov[4] = {oA.x+oB.x+bo.x, oA.y+oB.y+bo.y, oA.z+oB.z+bo.z, oA.w+oB.w+bo.w};

            float hq[4];
            #pragma unroll
            for (int q = 0; q < 4; q++) {
                float cc = sigm(fv[q])*c_reg[q] + sigm(iv[q])*tanhf(gv[q]);
                c_reg[q] = cc;
                hq[q] = to_tf32(sigm(ov[q])*tanhf(cc));
            }
            float* hp = g_hist + (size_t)s*NH + (size_t)(n0 + n_l)*HID + hb*32 + jg*4;
            *(float4*)hp = make_float4(hq[0], hq[1], hq[2], hq[3]);
        }

        __syncthreads();
        CLUSTER_SYNC();                         // release hist[s] to hb-peers; full step barrier
    }
}

// ------------- projection: out[m][o] = hist[m][:] . W_out[o][:] + b_out[o] -------------
__global__ void __launch_bounds__(256, 2) proj_kernel(const float* __restrict__ b_out,
                                                      float* __restrict__ out) {
    extern __shared__ float sm[];
    float* sA = sm;                 // [128][PPITCH] hist tile; reused as park
    float* sB = sm + 128*PPITCH;    // [64][PPITCH]  W_out slice
    const int tid = threadIdx.x;
    const int m0 = blockIdx.x*128;
    const int n0 = blockIdx.y*64;

    for (int e = tid; e < 128*32; e += 256) {
        int r = e >> 5, c4 = e & 31;
        *(float4*)&sA[r*PPITCH + c4*4] = *(const float4*)(g_hist + (size_t)(m0+r)*HID + c4*4);
    }
    for (int e = tid; e < 64*32; e += 256) {
        int r = e >> 5, c4 = e & 31;
        *(float4*)&sB[r*PPITCH + c4*4] = *(const float4*)(g_Wout_p + (size_t)(n0+r)*HID + c4*4);
    }
    __syncthreads();

    const int w = tid >> 5;
    const int wm = w & 3, wn = w >> 2;
    wmma::fragment<wmma::accumulator,16,16,8,float> c[2][2];
    #pragma unroll
    for (int i=0;i<2;i++) { wmma::fill_fragment(c[i][0],0.f); wmma::fill_fragment(c[i][1],0.f); }

    #pragma unroll
    for (int k = 0; k < HID; k += 8) {
        wmma::fragment<wmma::matrix_a,16,16,8,wmma::precision::tf32,wmma::row_major> a0,a1;
        wmma::fragment<wmma::matrix_b,16,16,8,wmma::precision::tf32,wmma::col_major> b0,b1;
        wmma::load_matrix_sync(a0, &sA[(wm*32     )*PPITCH + k], PPITCH);
        wmma::load_matrix_sync(a1, &sA[(wm*32 + 16)*PPITCH + k], PPITCH);
        wmma::load_matrix_sync(b0, &sB[(wn*32     )*PPITCH + k], PPITCH);
        wmma::load_matrix_sync(b1, &sB[(wn*32 + 16)*PPITCH + k], PPITCH);
        wmma::mma_sync(c[0][0], a0, b0, c[0][0]);
        wmma::mma_sync(c[0][1], a0, b1, c[0][1]);
        wmma::mma_sync(c[1][0], a1, b0, c[1][0]);
        wmma::mma_sync(c[1][1], a1, b1, c[1][1]);
    }
    __syncthreads();
    #pragma unroll
    for (int i=0;i<2;i++)
        #pragma unroll
        for (int j=0;j<2;j++)
            wmma::store_matrix_sync(&sA[(wm*32 + i*16)*PPITCH + wn*32 + j*16],
                                    c[i][j], PPITCH, wmma::mem_row_major);
    __syncthreads();

    for (int e = tid; e < 128*16; e += 256) {
        int r = e >> 4, c4 = e & 15;
        const float* p = &sA[r*PPITCH + c4*4];
        const float* b = &b_out[n0 + c4*4];
        float4 v = make_float4(p[0]+b[0], p[1]+b[1], p[2]+b[2], p[3]+b[3]);
        *(float4*)&out[(size_t)(m0 + r)*OUTDIM + n0 + c4*4] = v;
    }
}

extern "C" void kernel_launch(void* const* d_in, const int* in_sizes, int n_in,
                              void* d_out, int out_size) {
    const float* x     = (const float*)d_in[0];
    const float* W_ih  = (const float*)d_in[1];
    const float* W_hh  = (const float*)d_in[2];
    const float* b_ih  = (const float*)d_in[3];
    const float* b_hh  = (const float*)d_in[4];
    const float* W_out = (const float*)d_in[5];
    const float* b_out = (const float*)d_in[6];
    float* out = (float*)d_out;
    (void)in_sizes; (void)n_in; (void)out_size;

    cudaFuncSetAttribute(lstm_persist_kernel, cudaFuncAttributeMaxDynamicSharedMemorySize, STEP_SMEM);
    cudaFuncSetAttribute(proj_kernel,         cudaFuncAttributeMaxDynamicSharedMemorySize, PROJ_SMEM);

    pack_kernel<<<512, 256>>>(W_ih, W_hh, b_ih, b_hh, W_out);

    lstm_persist_kernel<<<dim3(32, 4), 512, STEP_SMEM>>>(x);

    proj_kernel<<<dim3(M_ALL/128, OUTDIM/64), 256, PROJ_SMEM>>>(b_out, out);
}